// round 4
// baseline (speedup 1.0000x reference)
#include <cuda_runtime.h>
#include <math.h>

#define BATCH 2
#define T 8
#define C 64
#define R 16
#define H 160
#define W 160
#define HW (H*W)            // 25600
#define CHW (C*HW)          // 1,638,400
#define TCHW (T*CHW)
#define C2 128
#define C4 256

typedef unsigned long long ull;

__device__ __forceinline__ ull pk2(float a, float b) {
    ull r; asm("mov.b64 %0, {%1,%2};" : "=l"(r) : "f"(a), "f"(b)); return r;
}
__device__ __forceinline__ float2 upk2(ull v) {
    float2 r; asm("mov.b64 {%0,%1}, %2;" : "=f"(r.x), "=f"(r.y) : "l"(v)); return r;
}
__device__ __forceinline__ void ffma2(ull& d, ull a, ull b) {
    asm("fma.rn.f32x2 %0, %1, %2, %0;" : "+l"(d) : "l"(a), "l"(b));
}
__device__ __forceinline__ ull d2u(double d) { return __double_as_longlong(d); }

// ---------------- scratch (device globals) -------------------------------------
__device__ float g_pool[BATCH*C];
__device__ float g_wd[BATCH*C*9];
__device__ float g_fp[BATCH*CHW];                    // 13.1 MB
__device__ float g_fusion[(size_t)BATCH*C2*HW];      // 26.2 MB
__device__ float g_t1[(size_t)BATCH*C4*HW];          // 52.4 MB
__device__ float g_g1[BATCH*CHW];                    // 13.1 MB
__device__ float g_eb[2][C];                         // effective bias per gate

// ---------------- pool ----------------------------------------------------------
__global__ void pool_kernel(const float* __restrict__ xbase) {
    int plane = blockIdx.x;
    int bi = plane >> 6, c = plane & 63;
    const float* p = xbase + (size_t)bi*TCHW + (size_t)c*HW;
    float s = 0.f;
    for (int i = threadIdx.x; i < HW; i += 256) s += p[i];
    __shared__ float red[8];
    #pragma unroll
    for (int o = 16; o; o >>= 1) s += __shfl_down_sync(0xffffffffu, s, o);
    if ((threadIdx.x & 31) == 0) red[threadIdx.x >> 5] = s;
    __syncthreads();
    if (threadIdx.x == 0) {
        float t = 0.f;
        #pragma unroll
        for (int k = 0; k < 8; k++) t += red[k];
        g_pool[plane] = t * (1.0f / (float)HW);
    }
}

// ---------------- tiny MLP ------------------------------------------------------
__global__ void mlp_kernel(const float* __restrict__ w1,
                           const float* __restrict__ gamma,
                           const float* __restrict__ beta,
                           const float* __restrict__ mean,
                           const float* __restrict__ var,
                           const float* __restrict__ w2,
                           const float* __restrict__ b2) {
    __shared__ float zs[BATCH*R];
    int tid = threadIdx.x;
    if (tid < BATCH*R) {
        int bi = tid / R, j = tid % R;
        float s = 0.f;
        for (int c = 0; c < C; c++) s = fmaf(g_pool[bi*C + c], w1[j*C + c], s);
        s = (s - mean[j]) * rsqrtf(var[j] + 1e-5f) * gamma[j] + beta[j];
        zs[tid] = fmaxf(s, 0.f);
    }
    __syncthreads();
    for (int o = tid; o < BATCH*C*9; o += blockDim.x) {
        int bi = o / (C*9), oo = o % (C*9);
        float s = b2[oo];
        #pragma unroll
        for (int j = 0; j < R; j++) s = fmaf(zs[bi*R + j], w2[oo*R + j], s);
        g_wd[o] = s;
    }
}

// ---------------- effective bias precompute (once per launch) ------------------
__global__ void prep_eb_kernel(const float* __restrict__ po1_w, const float* __restrict__ po1_b,
                               const float* __restrict__ dw1_b,
                               const float* __restrict__ po2_w, const float* __restrict__ po2_b,
                               const float* __restrict__ dw2_b) {
    int t = threadIdx.x;          // 128 threads
    int gate = t >> 6, o = t & 63;
    const float* pw = gate ? po2_w : po1_w;
    const float* pb = gate ? po2_b : po1_b;
    const float* db = gate ? dw2_b : dw1_b;
    float s = pb[o];
    for (int ch = 0; ch < C4; ch++) s = fmaf(pw[o*C4 + ch], db[ch], s);
    g_eb[gate][o] = s;
}

// ---------------- dynamic depthwise 3x3 -----------------------------------------
__global__ void dyndw_kernel(const float* __restrict__ ybase,
                             const float* __restrict__ kc_bias) {
    int idx = blockIdx.x * 256 + threadIdx.x;
    int px = idx % HW;
    int plane = idx / HW;
    int c = plane & 63, bi = plane >> 6;
    const float* p = ybase + (size_t)bi*TCHW + (size_t)c*HW;
    const float* wp = g_wd + plane*9;
    float w[9];
    #pragma unroll
    for (int k = 0; k < 9; k++) w[k] = wp[k];
    int y0 = px / W, x0 = px % W;
    float s = 0.f;
    #pragma unroll
    for (int kh = 0; kh < 3; kh++) {
        int yy = y0 + kh - 1;
        if ((unsigned)yy >= H) continue;
        const float* row = p + yy*W;
        #pragma unroll
        for (int kw = 0; kw < 3; kw++) {
            int xx = x0 + kw - 1;
            if ((unsigned)xx < W) s = fmaf(row[xx], w[kh*3 + kw], s);
        }
    }
    g_fp[idx] = s + kc_bias[c];
}

// ---------------- conv3x3 128->128 + leaky, packed f32x2 ------------------------
// block 256 thr; tile 32x16 px, 32 oc; per-thread 8px x 8oc as 4 px-pairs.
// grid (5, 10, BATCH*4)
__global__ void __launch_bounds__(256, 2) conv3x3_kernel(const float* __restrict__ xbase,
                                                         const float* __restrict__ wgt,
                                                         const float* __restrict__ bias) {
    __shared__ __align__(16) float tile_s[18*35];
    __shared__ __align__(16) float wsd[9*64];    // [tap][32 oc duplicated]
    int tid = threadIdx.x;
    int pc = tid & 3;
    int ty = (tid >> 2) & 15;
    int og = tid >> 6;                           // 0..3
    int x0 = blockIdx.x * 32;
    int y0 = blockIdx.y * 16;
    int bz = blockIdx.z;
    int bi = bz >> 2;
    int oc0 = (bz & 3) * 32;

    const float* xp  = xbase + (size_t)bi*TCHW;
    const float* fpp = g_fp  + (size_t)bi*CHW;

    // precompute tile-load positions (up to 3 per thread, 612 = 18x34 total)
    // smok: slot exists in smem (always store, zero-fill halo)
    // tval: global coords in range (gate the load)
    int toff[3], tsm[3]; bool tval[3], smok[3];
    #pragma unroll
    for (int l = 0; l < 3; l++) {
        int s = tid + l*256;
        int r = s / 34, cc = s - r*34;
        int gy = y0 + r - 1, gx = x0 + cc - 1;
        bool ok = (s < 612);
        bool v = ok && ((unsigned)gy < H) && ((unsigned)gx < W);
        smok[l] = ok;
        toff[l] = v ? gy*W + gx : 0;
        tval[l] = v;
        tsm[l]  = ok ? (r*35 + cc) : 0;
    }
    // weight staging positions (288 = 32oc x 9)
    int wo0 = tid / 9,        wk0 = tid % 9;
    int wo1 = (tid+256) / 9,  wk1 = (tid+256) % 9;
    bool wv0 = tid < 288, wv1 = tid < 32;
    size_t wg0 = ((size_t)(oc0 + wo0)*C2)*9 + wk0;
    size_t wg1 = ((size_t)(oc0 + wo1)*C2)*9 + wk1;
    int wsm0 = wk0*64 + wo0*2, wsm1 = wk1*64 + wo1*2;

    ull acc[4][8];
    #pragma unroll
    for (int k = 0; k < 4; k++)
        #pragma unroll
        for (int o = 0; o < 8; o++) acc[k][o] = 0ull;

    // prefetch ic=0
    float tv[3], pw0 = 0.f, pw1 = 0.f;
    {
        const float* src = xp;   // ic=0
        #pragma unroll
        for (int l = 0; l < 3; l++) tv[l] = tval[l] ? __ldg(src + toff[l]) : 0.f;
        if (wv0) pw0 = __ldg(wgt + wg0);
        if (wv1) pw1 = __ldg(wgt + wg1);
    }

    int vbase0 = ty*35 + pc*8;

    for (int ic = 0; ic < C2; ic++) {
        __syncthreads();
        #pragma unroll
        for (int l = 0; l < 3; l++) if (smok[l]) tile_s[tsm[l]] = tv[l];
        if (wv0) { wsd[wsm0] = pw0; wsd[wsm0+1] = pw0; }
        if (wv1) { wsd[wsm1] = pw1; wsd[wsm1+1] = pw1; }
        __syncthreads();

        if (ic + 1 < C2) {
            int icn = ic + 1;
            const float* src = (icn < C) ? (xp + (size_t)icn*HW) : (fpp + (size_t)(icn - C)*HW);
            #pragma unroll
            for (int l = 0; l < 3; l++) tv[l] = tval[l] ? __ldg(src + toff[l]) : 0.f;
            if (wv0) pw0 = __ldg(wgt + wg0 + (size_t)icn*9);
            if (wv1) pw1 = __ldg(wgt + wg1 + (size_t)icn*9);
        }

        #pragma unroll
        for (int kh = 0; kh < 3; kh++) {
            int vb = vbase0 + kh*35;
            float v[10];
            #pragma unroll
            for (int j = 0; j < 10; j++) v[j] = tile_s[vb + j];
            ull E[5], O[4];
            #pragma unroll
            for (int k = 0; k < 5; k++) E[k] = pk2(v[2*k], v[2*k+1]);
            #pragma unroll
            for (int k = 0; k < 4; k++) O[k] = pk2(v[2*k+1], v[2*k+2]);
            #pragma unroll
            for (int kw = 0; kw < 3; kw++) {
                int tap = kh*3 + kw;
                const float* wb = wsd + tap*64 + og*16;
                #pragma unroll
                for (int op = 0; op < 4; op++) {
                    double2 w2 = ((const double2*)wb)[op];
                    ull wA = d2u(w2.x), wB = d2u(w2.y);
                    #pragma unroll
                    for (int k = 0; k < 4; k++) {
                        ull P = (kw == 0) ? E[k] : (kw == 1) ? O[k] : E[k+1];
                        ffma2(acc[k][2*op],   P, wA);
                        ffma2(acc[k][2*op+1], P, wB);
                    }
                }
            }
        }
    }

    // epilogue: bias + leaky relu + store
    int row = y0 + ty;
    #pragma unroll
    for (int o = 0; o < 8; o++) {
        int oc = oc0 + og*8 + o;
        float bv = bias[oc];
        float r8[8];
        #pragma unroll
        for (int k = 0; k < 4; k++) {
            float2 p = upk2(acc[k][o]);
            float a = p.x + bv, b = p.y + bv;
            r8[2*k]   = (a > 0.f) ? a : 0.1f*a;
            r8[2*k+1] = (b > 0.f) ? b : 0.1f*b;
        }
        float* op = g_fusion + ((size_t)bi*C2 + oc)*HW + (size_t)row*W + x0 + pc*8;
        ((float4*)op)[0] = make_float4(r8[0], r8[1], r8[2], r8[3]);
        ((float4*)op)[1] = make_float4(r8[4], r8[5], r8[6], r8[7]);
    }
}

// ---------------- pointwise expand 64 -> 128 oc per block, packed ----------------
// grid (HW/128, 2 oc-halves, BATCH); 256 thr; per-thread 8px x 8oc.
// dyn smem: in_s[64][132] + wdup[64][260]   (260: 16B-aligned row stride)
#define EXP_SMEM (64*132*4 + 64*260*4)
__global__ void __launch_bounds__(256, 2) expand_kernel(int halfoff,
                                                        const float* __restrict__ wgt,   // [256][64]
                                                        const float* __restrict__ bias) {
    extern __shared__ __align__(16) float sm[];
    float* in_s = sm;                 // 64 x 132
    float* wdup = sm + 64*132;        // 64 x 260 (oc duplicated pairs, padded)
    int tid = threadIdx.x;
    int bi  = blockIdx.z;
    int och = blockIdx.y;             // oc half: 0 or 1 (128 oc each)
    int px0 = blockIdx.x * 128;
    int pg = tid & 15;                // 16 px groups x 8 px
    int og = tid >> 4;                // 16 oc groups x 8 oc

    const float* in = g_fusion + ((size_t)bi*C2 + halfoff)*HW + px0;
    // stage input: 64ic x 128px (float4)
    #pragma unroll
    for (int rr = 0; rr < 8; rr++) {
        int s = tid + rr*256;
        int ic = s >> 5, p4 = s & 31;
        float4 v = ((const float4*)(in + (size_t)ic*HW))[p4];
        *((float4*)&in_s[ic*132 + p4*4]) = v;
    }
    // stage weights duplicated: wdup[ic][2*ocl] = wdup[ic][2*ocl+1] = wgt[och*128+ocl][ic]
    #pragma unroll
    for (int rr = 0; rr < 32; rr++) {
        int s = tid + rr*256;
        int ocl = s >> 6, ic = s & 63;
        float v = wgt[(size_t)(och*128 + ocl)*C + ic];
        wdup[ic*260 + 2*ocl]     = v;
        wdup[ic*260 + 2*ocl + 1] = v;
    }
    __syncthreads();

    ull acc[4][8];
    #pragma unroll
    for (int k = 0; k < 4; k++)
        #pragma unroll
        for (int o = 0; o < 8; o++) acc[k][o] = 0ull;

    #pragma unroll 4
    for (int ic = 0; ic < C; ic++) {
        double2 A0 = *((const double2*)&in_s[ic*132 + pg*8]);
        double2 A1 = *((const double2*)&in_s[ic*132 + pg*8 + 4]);
        ull P[4] = { d2u(A0.x), d2u(A0.y), d2u(A1.x), d2u(A1.y) };
        const float* wb = wdup + ic*260 + og*16;
        #pragma unroll
        for (int op = 0; op < 4; op++) {
            double2 w2 = ((const double2*)wb)[op];
            ull wA = d2u(w2.x), wB = d2u(w2.y);
            #pragma unroll
            for (int k = 0; k < 4; k++) {
                ffma2(acc[k][2*op],   P[k], wA);
                ffma2(acc[k][2*op+1], P[k], wB);
            }
        }
    }

    #pragma unroll
    for (int o = 0; o < 8; o++) {
        int oc = och*128 + og*8 + o;
        float bv = bias[oc];
        float2 p0 = upk2(acc[0][o]), p1 = upk2(acc[1][o]);
        float2 p2 = upk2(acc[2][o]), p3 = upk2(acc[3][o]);
        float* op = g_t1 + ((size_t)bi*C4 + oc)*HW + px0 + pg*8;
        ((float4*)op)[0] = make_float4(p0.x+bv, p0.y+bv, p1.x+bv, p1.y+bv);
        ((float4*)op)[1] = make_float4(p2.x+bv, p2.y+bv, p3.x+bv, p3.y+bv);
    }
}

// ---------------- fused dw3x3 + contract(256->64) + sigmoid [+combine] ----------
// grid (5, 20, BATCH); tile 32x8 px, 1 px/thread, 64 oc as 32 packed pairs.
// dyn smem: w_s[256][68] + wd_s[2304] + t_s[16][10][35]   (68: 16B row stride)
#define GF_SMEM (256*68*4 + 2304*4 + 16*350*4)
template<bool FINAL>
__global__ void __launch_bounds__(256, 2) gatefuse_kernel(const float* __restrict__ po_w,  // [64][256]
                                                          const float* __restrict__ dw_w,  // [256][9]
                                                          int gate,
                                                          float* __restrict__ outbase) {
    extern __shared__ __align__(16) float sm[];
    float* w_s  = sm;                       // 256 x 68 (oc row, padded)
    float* wd_s = sm + 256*68;              // 256 x 9
    float* t_s  = sm + 256*68 + 2304;       // 16 x 10 x 35
    int tid = threadIdx.x;
    int bi  = blockIdx.z;
    int px0 = blockIdx.x * 32;
    int py0 = blockIdx.y * 8;
    int c = tid & 31, r = tid >> 5;

    // stage po weights transposed: w_s[ch][oc]
    #pragma unroll
    for (int rr = 0; rr < 64; rr++) {
        int s = tid + rr*256;
        int oc = s >> 8, ch = s & 255;
        w_s[ch*68 + oc] = po_w[(size_t)oc*C4 + ch];
    }
    // stage dw weights
    #pragma unroll
    for (int rr = 0; rr < 9; rr++) {
        int s = tid + rr*256;
        if (s < 2304) wd_s[s] = dw_w[s];
    }

    // tile-load positions: 340 = 10x34, each thread <=2
    int p0 = tid, p1 = tid + 256;
    int r0 = p0 / 34, c0 = p0 - r0*34;
    int r1 = p1 / 34, c1 = p1 - r1*34;
    int gy0 = py0 + r0 - 1, gx0 = px0 + c0 - 1;
    int gy1 = py0 + r1 - 1, gx1 = px0 + c1 - 1;
    bool v0 = ((unsigned)gy0 < H) && ((unsigned)gx0 < W);
    bool v1 = (p1 < 340) && ((unsigned)gy1 < H) && ((unsigned)gx1 < W);
    int go0 = v0 ? gy0*W + gx0 : 0;
    int go1 = v1 ? gy1*W + gx1 : 0;
    int so0 = r0*35 + c0, so1 = r1*35 + c1;

    const float* in = g_t1 + (size_t)bi*C4*HW;

    ull acc[32];
    #pragma unroll
    for (int j = 0; j < 32; j++) acc[j] = 0ull;

    int vb = r*35 + c;

    for (int ch0 = 0; ch0 < C4; ch0 += 16) {
        __syncthreads();
        #pragma unroll
        for (int chl = 0; chl < 16; chl++) {
            const float* src = in + (size_t)(ch0 + chl)*HW;
            t_s[chl*350 + so0] = v0 ? __ldg(src + go0) : 0.f;
            if (p1 < 340) t_s[chl*350 + so1] = v1 ? __ldg(src + go1) : 0.f;
        }
        __syncthreads();

        #pragma unroll
        for (int chl = 0; chl < 16; chl++) {
            int ch = ch0 + chl;
            const float* wk = wd_s + ch*9;
            const float* tb = t_s + chl*350 + vb;
            float dwv = 0.f;
            #pragma unroll
            for (int kh = 0; kh < 3; kh++)
                #pragma unroll
                for (int kw = 0; kw < 3; kw++)
                    dwv = fmaf(tb[kh*35 + kw], wk[kh*3 + kw], dwv);
            ull dv = pk2(dwv, dwv);
            const float* wrow = w_s + ch*68;
            #pragma unroll
            for (int o2 = 0; o2 < 16; o2++) {
                double2 w2 = ((const double2*)wrow)[o2];
                ffma2(acc[2*o2],   dv, d2u(w2.x));
                ffma2(acc[2*o2+1], dv, d2u(w2.y));
            }
        }
    }

    // epilogue
    int px = (py0 + r)*W + px0 + c;
    const float* eb = g_eb[gate];
    #pragma unroll
    for (int j = 0; j < 32; j++) {
        float2 p = upk2(acc[j]);
        #pragma unroll
        for (int h = 0; h < 2; h++) {
            int o = 2*j + h;
            float x = ((h == 0) ? p.x : p.y) + eb[o];
            float g = 1.0f / (1.0f + __expf(-x));
            if (!FINAL) {
                g_g1[((size_t)bi*C + o)*HW + px] = g;
            } else {
                float f1 = g_fusion[((size_t)bi*C2 + o)*HW + px];
                float f2 = g_fusion[((size_t)bi*C2 + C + o)*HW + px];
                float g1 = g_g1[((size_t)bi*C + o)*HW + px];
                outbase[(size_t)bi*TCHW + (size_t)o*HW + px] = f1*g1 + f2*g;
            }
        }
    }
}

// ---------------- launcher -------------------------------------------------------
extern "C" void kernel_launch(void* const* d_in, const int* in_sizes, int n_in,
                              void* d_out, int out_size) {
    (void)in_sizes; (void)n_in; (void)out_size;
    const float* feature   = (const float*)d_in[0];
    const float* kc_w1     = (const float*)d_in[1];
    const float* kc_gamma  = (const float*)d_in[2];
    const float* kc_beta   = (const float*)d_in[3];
    const float* kc_mean   = (const float*)d_in[4];
    const float* kc_var    = (const float*)d_in[5];
    const float* kc_w2     = (const float*)d_in[6];
    const float* kc_b2     = (const float*)d_in[7];
    const float* kc_bias   = (const float*)d_in[8];
    const float* conv1_w   = (const float*)d_in[9];
    const float* conv1_b   = (const float*)d_in[10];
    const float* pi1_w     = (const float*)d_in[11];
    const float* pi1_b     = (const float*)d_in[12];
    const float* dw1_w     = (const float*)d_in[13];
    const float* dw1_b     = (const float*)d_in[14];
    const float* po1_w     = (const float*)d_in[15];
    const float* po1_b     = (const float*)d_in[16];
    const float* pi2_w     = (const float*)d_in[17];
    const float* pi2_b     = (const float*)d_in[18];
    const float* dw2_w     = (const float*)d_in[19];
    const float* dw2_b     = (const float*)d_in[20];
    const float* po2_w     = (const float*)d_in[21];
    const float* po2_b     = (const float*)d_in[22];
    float* out = (float*)d_out;

    static bool attr_done = false;
    if (!attr_done) {
        cudaFuncSetAttribute(expand_kernel, cudaFuncAttributeMaxDynamicSharedMemorySize, EXP_SMEM);
        cudaFuncSetAttribute(gatefuse_kernel<false>, cudaFuncAttributeMaxDynamicSharedMemorySize, GF_SMEM);
        cudaFuncSetAttribute(gatefuse_kernel<true>,  cudaFuncAttributeMaxDynamicSharedMemorySize, GF_SMEM);
        attr_done = true;
    }

    // out[:, T-1] = feature[:, T-1]
    for (int bi = 0; bi < BATCH; bi++) {
        size_t off = ((size_t)bi*T + (T-1)) * CHW;
        cudaMemcpyAsync(out + off, feature + off, (size_t)CHW*sizeof(float),
                        cudaMemcpyDeviceToDevice, 0);
    }

    prep_eb_kernel<<<1, 128>>>(po1_w, po1_b, dw1_b, po2_w, po2_b, dw2_b);

    for (int i = T - 2; i >= 0; --i) {
        const float* xbase = feature + (size_t)i*CHW;
        const float* ybase = out + (size_t)(i+1)*CHW;

        pool_kernel<<<BATCH*C, 256>>>(xbase);
        mlp_kernel<<<1, 128>>>(kc_w1, kc_gamma, kc_beta, kc_mean, kc_var, kc_w2, kc_b2);
        dyndw_kernel<<<(BATCH*CHW)/256, 256>>>(ybase, kc_bias);
        conv3x3_kernel<<<dim3(5, 10, BATCH*4), 256>>>(xbase, conv1_w, conv1_b);

        // gate 1 -> g_g1
        expand_kernel<<<dim3(HW/128, 2, BATCH), 256, EXP_SMEM>>>(0, pi1_w, pi1_b);
        gatefuse_kernel<false><<<dim3(5, 20, BATCH), 256, GF_SMEM>>>(po1_w, dw1_w, 0, nullptr);

        // gate 2 -> fused final combine into out[:, i]
        expand_kernel<<<dim3(HW/128, 2, BATCH), 256, EXP_SMEM>>>(C, pi2_w, pi2_b);
        gatefuse_kernel<true><<<dim3(5, 20, BATCH), 256, GF_SMEM>>>(po2_w, dw2_w, 1, out + (size_t)i*CHW);
    }
}